// round 1
// baseline (speedup 1.0000x reference)
#include <cuda_runtime.h>

#define NTOK 4096
#define CDIM 768
#define C3   2304
#define TPL  16
#define NH   12
#define HD   64

// Scratch (no allocs allowed): ~58 MB of __device__ globals.
__device__ float g_qkv_w[C3 * CDIM];   // (2304, 768)  reduced template weight
__device__ float g_qkv[NTOK * C3];     // (4096, 2304) qkv activations
__device__ float g_att[NTOK * CDIM];   // (4096, 768)  attention output (pre-proj)

// ---------------------------------------------------------------------------
// Kernel 1: qkv_w[o,i] = sum_t w[t] * templates[t,o,i],  w[t]=(c[0,t]+c[1,t])/2
// Pure HBM streaming: 113 MB read / 7 MB write.
// ---------------------------------------------------------------------------
__global__ void k_build_w(const float* __restrict__ tpl, const float* __restrict__ coef) {
    __shared__ float w[TPL];
    if (threadIdx.x < TPL)
        w[threadIdx.x] = 0.5f * (coef[threadIdx.x] + coef[TPL + threadIdx.x]);
    __syncthreads();
    const int TOT = C3 * CDIM / 4;   // float4 count = 442368
    int idx = blockIdx.x * blockDim.x + threadIdx.x;
    if (idx >= TOT) return;
    const float4* t4 = (const float4*)tpl;
    float4 acc = make_float4(0.f, 0.f, 0.f, 0.f);
#pragma unroll
    for (int t = 0; t < TPL; t++) {
        float4 v = t4[(size_t)t * TOT + idx];
        float wt = w[t];
        acc.x = fmaf(wt, v.x, acc.x);
        acc.y = fmaf(wt, v.y, acc.y);
        acc.z = fmaf(wt, v.z, acc.z);
        acc.w = fmaf(wt, v.w, acc.w);
    }
    ((float4*)g_qkv_w)[idx] = acc;
}

// ---------------------------------------------------------------------------
// Tiled SGEMM (TN): Y[M,Nd] = A[M,K] @ B[Nd,K]^T + bias[Nd]
// BM=BN=128, BK=16, 256 threads, 8x8 micro-tile per thread.
// A staged transposed in smem (As[k][m]) for broadcast/vector-friendly reads.
// All dims here are multiples of tiles, so no edge guards.
// ---------------------------------------------------------------------------
__device__ __forceinline__ void gemm_tn(const float* __restrict__ A,
                                        const float* __restrict__ Bm,
                                        const float* __restrict__ bias,
                                        float* __restrict__ Y,
                                        int M, int Nd, int K) {
    const int BK = 16;
    __shared__ float As[BK][132];   // pad 132: conflict-free transposed stores
    __shared__ float Bs[BK][132];

    int tid = threadIdx.x;
    int ty = tid >> 4;        // 0..15
    int tx = tid & 15;        // 0..15
    int m0 = blockIdx.y * 128;
    int n0 = blockIdx.x * 128;

    float acc[8][8];
#pragma unroll
    for (int i = 0; i < 8; i++)
#pragma unroll
        for (int j = 0; j < 8; j++) acc[i][j] = 0.f;

    for (int k0 = 0; k0 < K; k0 += BK) {
#pragma unroll
        for (int l = 0; l < 2; l++) {      // A tile: 128x16 = 512 float4
            int vid = tid + l * 256;
            int row = vid >> 2, kq = vid & 3;
            float4 v = *(const float4*)(A + (size_t)(m0 + row) * K + k0 + kq * 4);
            As[kq * 4 + 0][row] = v.x;
            As[kq * 4 + 1][row] = v.y;
            As[kq * 4 + 2][row] = v.z;
            As[kq * 4 + 3][row] = v.w;
        }
#pragma unroll
        for (int l = 0; l < 2; l++) {      // B tile
            int vid = tid + l * 256;
            int row = vid >> 2, kq = vid & 3;
            float4 v = *(const float4*)(Bm + (size_t)(n0 + row) * K + k0 + kq * 4);
            Bs[kq * 4 + 0][row] = v.x;
            Bs[kq * 4 + 1][row] = v.y;
            Bs[kq * 4 + 2][row] = v.z;
            Bs[kq * 4 + 3][row] = v.w;
        }
        __syncthreads();
#pragma unroll
        for (int kk = 0; kk < BK; kk++) {
            float a[8], b[8];
#pragma unroll
            for (int i = 0; i < 8; i++) a[i] = As[kk][ty * 8 + i];
#pragma unroll
            for (int j = 0; j < 8; j++) b[j] = Bs[kk][tx * 8 + j];
#pragma unroll
            for (int i = 0; i < 8; i++)
#pragma unroll
                for (int j = 0; j < 8; j++)
                    acc[i][j] = fmaf(a[i], b[j], acc[i][j]);
        }
        __syncthreads();
    }

    // Epilogue: vectorized stores + bias
#pragma unroll
    for (int i = 0; i < 8; i++) {
        int m = m0 + ty * 8 + i;
#pragma unroll
        for (int jg = 0; jg < 2; jg++) {
            int n = n0 + tx * 8 + jg * 4;
            float4 b4 = *(const float4*)(bias + n);
            float4 v;
            v.x = acc[i][jg * 4 + 0] + b4.x;
            v.y = acc[i][jg * 4 + 1] + b4.y;
            v.z = acc[i][jg * 4 + 2] + b4.z;
            v.w = acc[i][jg * 4 + 3] + b4.w;
            *(float4*)(Y + (size_t)m * Nd + n) = v;
        }
    }
}

__global__ void __launch_bounds__(256) k_gemm_qkv(const float* __restrict__ x,
                                                  const float* __restrict__ qb) {
    gemm_tn(x, g_qkv_w, qb, g_qkv, NTOK, C3, CDIM);
}

__global__ void __launch_bounds__(256) k_gemm_proj(const float* __restrict__ pw,
                                                   const float* __restrict__ pb,
                                                   float* __restrict__ out) {
    gemm_tn(g_att, pw, pb, out, NTOK, CDIM, CDIM);
}

// ---------------------------------------------------------------------------
// Kernel 3: flash attention, fp32, per (q-block of 64, head).
// 256 threads as 16x16; thread (ty,tx) owns rows {ty+16i} and cols {tx+16j}.
// Stride-65 smem rows + stride-16 row mapping => all LDS conflict-free or
// broadcast. Online softmax; Q pre-scaled by hd^-0.5 at load.
// ---------------------------------------------------------------------------
__global__ void __launch_bounds__(256) k_flash() {
    extern __shared__ float sm[];
    const int ST = 65;               // padded row stride (odd => CF strided reads)
    float* Qs = sm;                  // 64*65
    float* Ks = sm + 64 * ST;
    float* Vs = sm + 2 * 64 * ST;
    float* Ps = sm + 3 * 64 * ST;

    int tid = threadIdx.x;
    int ty = tid >> 4;
    int tx = tid & 15;
    int h  = blockIdx.y;
    int q0 = blockIdx.x * 64;
    const float scale = 0.125f;      // 64^-0.5

    // Load Q tile (scaled)
#pragma unroll
    for (int l = 0; l < 4; l++) {
        int vid = tid + l * 256;
        int m = vid >> 4, c4 = vid & 15;
        float4 v = *(const float4*)(g_qkv + (size_t)(q0 + m) * C3 + h * HD + c4 * 4);
        Qs[m * ST + c4 * 4 + 0] = v.x * scale;
        Qs[m * ST + c4 * 4 + 1] = v.y * scale;
        Qs[m * ST + c4 * 4 + 2] = v.z * scale;
        Qs[m * ST + c4 * 4 + 3] = v.w * scale;
    }

    float mi[4], li[4], acc[4][4];
#pragma unroll
    for (int i = 0; i < 4; i++) {
        mi[i] = -1e30f;
        li[i] = 0.f;
#pragma unroll
        for (int j = 0; j < 4; j++) acc[i][j] = 0.f;
    }

    for (int kb = 0; kb < NTOK / 64; kb++) {
        __syncthreads();   // prior AV done reading Ks/Vs/Ps
        int k0 = kb * 64;
#pragma unroll
        for (int l = 0; l < 4; l++) {
            int vid = tid + l * 256;
            int m = vid >> 4, c4 = vid & 15;
            float4 v = *(const float4*)(g_qkv + (size_t)(k0 + m) * C3 + CDIM + h * HD + c4 * 4);
            Ks[m * ST + c4 * 4 + 0] = v.x;
            Ks[m * ST + c4 * 4 + 1] = v.y;
            Ks[m * ST + c4 * 4 + 2] = v.z;
            Ks[m * ST + c4 * 4 + 3] = v.w;
            float4 u = *(const float4*)(g_qkv + (size_t)(k0 + m) * C3 + 2 * CDIM + h * HD + c4 * 4);
            Vs[m * ST + c4 * 4 + 0] = u.x;
            Vs[m * ST + c4 * 4 + 1] = u.y;
            Vs[m * ST + c4 * 4 + 2] = u.z;
            Vs[m * ST + c4 * 4 + 3] = u.w;
        }
        __syncthreads();

        // S = Q K^T (scaled)
        float s[4][4];
#pragma unroll
        for (int i = 0; i < 4; i++)
#pragma unroll
            for (int j = 0; j < 4; j++) s[i][j] = 0.f;
#pragma unroll 4
        for (int d = 0; d < HD; d++) {
            float q[4], k[4];
#pragma unroll
            for (int i = 0; i < 4; i++) q[i] = Qs[(ty + 16 * i) * ST + d];   // broadcast
#pragma unroll
            for (int j = 0; j < 4; j++) k[j] = Ks[(tx + 16 * j) * ST + d];   // CF (odd stride)
#pragma unroll
            for (int i = 0; i < 4; i++)
#pragma unroll
                for (int j = 0; j < 4; j++)
                    s[i][j] = fmaf(q[i], k[j], s[i][j]);
        }

        // Online softmax row stats (rows owned by 16 tx-lanes in a half-warp)
#pragma unroll
        for (int i = 0; i < 4; i++) {
            float mx = s[i][0];
#pragma unroll
            for (int j = 1; j < 4; j++) mx = fmaxf(mx, s[i][j]);
#pragma unroll
            for (int o = 8; o >= 1; o >>= 1)
                mx = fmaxf(mx, __shfl_xor_sync(0xffffffffu, mx, o));
            float mnew  = fmaxf(mi[i], mx);
            float alpha = __expf(mi[i] - mnew);
            float rs = 0.f;
#pragma unroll
            for (int j = 0; j < 4; j++) {
                float p = __expf(s[i][j] - mnew);
                s[i][j] = p;
                rs += p;
            }
#pragma unroll
            for (int o = 8; o >= 1; o >>= 1)
                rs += __shfl_xor_sync(0xffffffffu, rs, o);
            li[i] = li[i] * alpha + rs;
            mi[i] = mnew;
#pragma unroll
            for (int j = 0; j < 4; j++) acc[i][j] *= alpha;
        }

        // Publish P tile
#pragma unroll
        for (int i = 0; i < 4; i++)
#pragma unroll
            for (int j = 0; j < 4; j++)
                Ps[(ty + 16 * i) * ST + tx + 16 * j] = s[i][j];
        __syncthreads();

        // O += P V
#pragma unroll 4
        for (int m = 0; m < 64; m++) {
            float pv[4], vv[4];
#pragma unroll
            for (int i = 0; i < 4; i++) pv[i] = Ps[(ty + 16 * i) * ST + m];   // broadcast
#pragma unroll
            for (int j = 0; j < 4; j++) vv[j] = Vs[m * ST + tx + 16 * j];     // CF
#pragma unroll
            for (int i = 0; i < 4; i++)
#pragma unroll
                for (int j = 0; j < 4; j++)
                    acc[i][j] = fmaf(pv[i], vv[j], acc[i][j]);
        }
    }

    // Normalize + store to (N, C) layout with col = h*64 + d
#pragma unroll
    for (int i = 0; i < 4; i++) {
        float inv = 1.f / li[i];
        int r = q0 + ty + 16 * i;
#pragma unroll
        for (int j = 0; j < 4; j++)
            g_att[(size_t)r * CDIM + h * HD + tx + 16 * j] = acc[i][j] * inv;
    }
}

// ---------------------------------------------------------------------------
// Launch: 4 kernels on the default stream (sequential, graph-capturable).
// ---------------------------------------------------------------------------
extern "C" void kernel_launch(void* const* d_in, const int* in_sizes, int n_in,
                              void* d_out, int out_size) {
    const float* x         = (const float*)d_in[0];
    const float* templates = (const float*)d_in[1];
    const float* coeffs    = (const float*)d_in[2];
    const float* qkv_bias  = (const float*)d_in[3];
    const float* proj_w    = (const float*)d_in[4];
    const float* proj_b    = (const float*)d_in[5];
    float* out = (float*)d_out;

    // 1. template reduce -> qkv_w
    k_build_w<<<(C3 * CDIM / 4 + 255) / 256, 256>>>(templates, coeffs);

    // 2. qkv = x @ qkv_w^T + bias
    k_gemm_qkv<<<dim3(C3 / 128, NTOK / 128), 256>>>(x, qkv_bias);

    // 3. flash attention per (q-block, head)
    int smem = 4 * 64 * 65 * (int)sizeof(float);   // 66560 B
    cudaFuncSetAttribute(k_flash, cudaFuncAttributeMaxDynamicSharedMemorySize, smem);
    k_flash<<<dim3(NTOK / 64, NH), 256, smem>>>();

    // 4. out = att @ proj_w^T + proj_b
    k_gemm_proj<<<dim3(CDIM / 128, NTOK / 128), 256>>>(proj_w, proj_b, out);
}

// round 2
// speedup vs baseline: 2.7586x; 2.7586x over previous
#include <cuda_runtime.h>

#define NTOK 4096
#define CDIM 768
#define C3   2304
#define TPL  16
#define NH   12
#define HD   64

// Scratch (no allocs allowed): __device__ globals.
__device__ float g_qkv_w[C3 * CDIM];   // (2304, 768)  reduced template weight
__device__ float g_qkv[NTOK * C3];     // (4096, 2304) qkv activations
__device__ float g_att[NTOK * CDIM];   // (4096, 768)  attention output (pre-proj)

// ---------------------------------------------------------------------------
// helpers: tf32 round, ldmatrix, mma
// ---------------------------------------------------------------------------
__device__ __forceinline__ unsigned f2tf(float x) {
    unsigned r;
    asm("cvt.rna.tf32.f32 %0, %1;" : "=r"(r) : "f"(x));
    return r;
}
__device__ __forceinline__ float f2tff(float x) { return __uint_as_float(f2tf(x)); }

__device__ __forceinline__ void ldsm4(unsigned& r0, unsigned& r1, unsigned& r2, unsigned& r3,
                                      unsigned addr) {
    asm volatile("ldmatrix.sync.aligned.m8n8.x4.shared.b16 {%0,%1,%2,%3}, [%4];"
                 : "=r"(r0), "=r"(r1), "=r"(r2), "=r"(r3) : "r"(addr));
}
__device__ __forceinline__ void mma_tf32(float* d, const unsigned* a, unsigned b0, unsigned b1) {
    asm volatile(
        "mma.sync.aligned.m16n8k8.row.col.f32.tf32.tf32.f32 "
        "{%0,%1,%2,%3},{%4,%5,%6,%7},{%8,%9},{%0,%1,%2,%3};"
        : "+f"(d[0]), "+f"(d[1]), "+f"(d[2]), "+f"(d[3])
        : "r"(a[0]), "r"(a[1]), "r"(a[2]), "r"(a[3]), "r"(b0), "r"(b1));
}
__device__ __forceinline__ unsigned smem_u32(const void* p) {
    return (unsigned)__cvta_generic_to_shared(p);
}

// ---------------------------------------------------------------------------
// Kernel 1: qkv_w[o,i] = sum_t w[t] * templates[t,o,i],  w[t]=(c[0,t]+c[1,t])/2
// ---------------------------------------------------------------------------
__global__ void k_build_w(const float* __restrict__ tpl, const float* __restrict__ coef) {
    __shared__ float w[TPL];
    if (threadIdx.x < TPL)
        w[threadIdx.x] = 0.5f * (coef[threadIdx.x] + coef[TPL + threadIdx.x]);
    __syncthreads();
    const int TOT = C3 * CDIM / 4;
    int idx = blockIdx.x * blockDim.x + threadIdx.x;
    if (idx >= TOT) return;
    const float4* t4 = (const float4*)tpl;
    float4 acc = make_float4(0.f, 0.f, 0.f, 0.f);
#pragma unroll
    for (int t = 0; t < TPL; t++) {
        float4 v = t4[(size_t)t * TOT + idx];
        float wt = w[t];
        acc.x = fmaf(wt, v.x, acc.x);
        acc.y = fmaf(wt, v.y, acc.y);
        acc.z = fmaf(wt, v.z, acc.z);
        acc.w = fmaf(wt, v.w, acc.w);
    }
    ((float4*)g_qkv_w)[idx] = acc;
}

// ---------------------------------------------------------------------------
// tf32 tensor-core SGEMM (TN): Y[M,Nd] = A[M,K] @ B[Nd,K]^T + bias
// 128x128 block, BK=16, 256 threads = 8 warps (4x2), warp tile 32x64.
// smem stride 20 floats -> conflict-free ldmatrix + float4 staging.
// ---------------------------------------------------------------------------
__device__ __forceinline__ void gemm_tn_mma(const float* __restrict__ A,
                                            const float* __restrict__ Bm,
                                            const float* __restrict__ bias,
                                            float* __restrict__ Y,
                                            int Nd, int K) {
    __shared__ float As[128 * 20];
    __shared__ float Bs[128 * 20];

    int tid = threadIdx.x;
    int lane = tid & 31;
    int w = tid >> 5;
    int wm = w >> 1;          // 0..3
    int wn = w & 1;           // 0..1
    int g = lane >> 2, q = lane & 3;

    int m0 = blockIdx.y * 128;
    int n0 = blockIdx.x * 128;

    float acc[2][8][4];
#pragma unroll
    for (int mi = 0; mi < 2; mi++)
#pragma unroll
        for (int nt = 0; nt < 8; nt++)
#pragma unroll
            for (int e = 0; e < 4; e++) acc[mi][nt][e] = 0.f;

    int rowStage = tid & 127;
    int qdBase = tid >> 7;            // 0..1

    // ldmatrix address bases
    int roffA = ((lane >> 3) & 1) * 8 + (lane & 7);
    int coffA = (lane >> 4) * 4;
    int roffB = ((lane >> 4) & 1) * 8 + (lane & 7);
    int coffB = ((lane >> 3) & 1) * 4;
    unsigned aAddr = smem_u32(As + (32 * wm + roffA) * 20 + coffA);
    unsigned bAddr = smem_u32(Bs + (64 * wn + roffB) * 20 + coffB);

    for (int k0 = 0; k0 < K; k0 += 16) {
        __syncthreads();
#pragma unroll
        for (int l = 0; l < 2; l++) {
            int qd = qdBase + 2 * l;
            float4 va = *(const float4*)(A + (size_t)(m0 + rowStage) * K + k0 + 4 * qd);
            float* da = As + rowStage * 20 + 4 * qd;
            da[0] = f2tff(va.x); da[1] = f2tff(va.y); da[2] = f2tff(va.z); da[3] = f2tff(va.w);
            float4 vb = *(const float4*)(Bm + (size_t)(n0 + rowStage) * K + k0 + 4 * qd);
            float* db = Bs + rowStage * 20 + 4 * qd;
            db[0] = f2tff(vb.x); db[1] = f2tff(vb.y); db[2] = f2tff(vb.z); db[3] = f2tff(vb.w);
        }
        __syncthreads();
#pragma unroll
        for (int ks = 0; ks < 2; ks++) {
            unsigned af[2][4];
            ldsm4(af[0][0], af[0][1], af[0][2], af[0][3], aAddr + ks * 32);
            ldsm4(af[1][0], af[1][1], af[1][2], af[1][3], aAddr + 16 * 20 * 4 + ks * 32);
#pragma unroll
            for (int ntp = 0; ntp < 4; ntp++) {
                unsigned b0, b1, b2, b3;
                ldsm4(b0, b1, b2, b3, bAddr + ntp * (16 * 20 * 4) + ks * 32);
                mma_tf32(acc[0][2 * ntp + 0], af[0], b0, b1);
                mma_tf32(acc[0][2 * ntp + 1], af[0], b2, b3);
                mma_tf32(acc[1][2 * ntp + 0], af[1], b0, b1);
                mma_tf32(acc[1][2 * ntp + 1], af[1], b2, b3);
            }
        }
    }

    // Epilogue: rows m0+32wm+16mi+g(+8), cols n0+64wn+8nt+2q(+1)
#pragma unroll
    for (int mi = 0; mi < 2; mi++) {
        int r0 = m0 + 32 * wm + 16 * mi + g;
        int r1 = r0 + 8;
#pragma unroll
        for (int nt = 0; nt < 8; nt++) {
            int n = n0 + 64 * wn + 8 * nt + 2 * q;
            float2 b2 = *(const float2*)(bias + n);
            float2 v0, v1;
            v0.x = acc[mi][nt][0] + b2.x; v0.y = acc[mi][nt][1] + b2.y;
            v1.x = acc[mi][nt][2] + b2.x; v1.y = acc[mi][nt][3] + b2.y;
            *(float2*)(Y + (size_t)r0 * Nd + n) = v0;
            *(float2*)(Y + (size_t)r1 * Nd + n) = v1;
        }
    }
}

__global__ void __launch_bounds__(256) k_gemm_qkv(const float* __restrict__ x,
                                                  const float* __restrict__ qb) {
    gemm_tn_mma(x, g_qkv_w, qb, g_qkv, C3, CDIM);
}
__global__ void __launch_bounds__(256) k_gemm_proj(const float* __restrict__ pw,
                                                   const float* __restrict__ pb,
                                                   float* __restrict__ out) {
    gemm_tn_mma(g_att, pw, pb, out, CDIM, CDIM);
}

// ---------------------------------------------------------------------------
// Flash attention, tf32 tensor cores.
// Block = 128 q-rows x 1 head, 8 warps, warp owns 16 q-rows (no cross-warp
// softmax reduction). K staged row-major [64][68]; V staged TRANSPOSED
// [d=64][key=64] stride 68; P round-trips through warp-private smem rows.
// All ldmatrix phases conflict-free (stride 68 = 4 mod 32).
// ---------------------------------------------------------------------------
__global__ void __launch_bounds__(256) k_flash() {
    extern __shared__ float sm[];
    float* Ks = sm;                 // [64][68]
    float* Vt = sm + 64 * 68;       // [64][68]  rows=d, cols=key
    float* Ps = sm + 2 * 64 * 68;   // [128][68] Q staging, then P per warp

    int tid = threadIdx.x;
    int lane = tid & 31;
    int w = tid >> 5;
    int g = lane >> 2, q = lane & 3;
    int h = blockIdx.y;
    int q0 = blockIdx.x * 128;

    // ---- stage Q (scaled, tf32-rounded) ----
#pragma unroll
    for (int l = 0; l < 8; l++) {
        int row = tid & 127;
        int qd = (tid >> 7) + 2 * l;
        float4 v = *(const float4*)(g_qkv + (size_t)(q0 + row) * C3 + h * HD + 4 * qd);
        float* dst = Ps + row * 68 + 4 * qd;
        dst[0] = f2tff(v.x * 0.125f);
        dst[1] = f2tff(v.y * 0.125f);
        dst[2] = f2tff(v.z * 0.125f);
        dst[3] = f2tff(v.w * 0.125f);
    }
    __syncthreads();

    // ---- load Q fragments into registers (live whole kernel) ----
    int roffA = ((lane >> 3) & 1) * 8 + (lane & 7);
    int coffA = (lane >> 4) * 4;
    unsigned aAddr = smem_u32(Ps + (16 * w + roffA) * 68 + coffA);
    unsigned qf[8][4];
#pragma unroll
    for (int ks = 0; ks < 8; ks++)
        ldsm4(qf[ks][0], qf[ks][1], qf[ks][2], qf[ks][3], aAddr + ks * 32);

    // B-fragment bases for K and Vt
    int roffB = ((lane >> 4) & 1) * 8 + (lane & 7);
    int coffB = ((lane >> 3) & 1) * 4;
    unsigned kAddr = smem_u32(Ks + roffB * 68 + coffB);
    unsigned vAddr = smem_u32(Vt + roffB * 68 + coffB);

    float o[8][4];
#pragma unroll
    for (int nt = 0; nt < 8; nt++)
#pragma unroll
        for (int e = 0; e < 4; e++) o[nt][e] = 0.f;
    float mi0 = -1e30f, mi1 = -1e30f, li0 = 0.f, li1 = 0.f;

    // P store pointers (warp-private rows)
    float* p0base = Ps + (16 * w + g) * 68 + 2 * q;
    float* p1base = Ps + (16 * w + 8 + g) * 68 + 2 * q;

    for (int kb = 0; kb < NTOK / 64; kb++) {
        __syncthreads();   // everyone done reading Ks/Vt
        int k0 = kb * 64;
#pragma unroll
        for (int l = 0; l < 4; l++) {
            int row = tid & 63;
            int qd = (tid >> 6) + 4 * l;
            float4 kv = *(const float4*)(g_qkv + (size_t)(k0 + row) * C3 + CDIM + h * HD + 4 * qd);
            float* dk = Ks + row * 68 + 4 * qd;
            dk[0] = f2tff(kv.x); dk[1] = f2tff(kv.y); dk[2] = f2tff(kv.z); dk[3] = f2tff(kv.w);
            float4 vv = *(const float4*)(g_qkv + (size_t)(k0 + row) * C3 + 2 * CDIM + h * HD + 4 * qd);
            Vt[(4 * qd + 0) * 68 + row] = f2tff(vv.x);
            Vt[(4 * qd + 1) * 68 + row] = f2tff(vv.y);
            Vt[(4 * qd + 2) * 68 + row] = f2tff(vv.z);
            Vt[(4 * qd + 3) * 68 + row] = f2tff(vv.w);
        }
        __syncthreads();

        // ---- S = Q K^T ----
        float s[8][4];
#pragma unroll
        for (int nt = 0; nt < 8; nt++)
#pragma unroll
            for (int e = 0; e < 4; e++) s[nt][e] = 0.f;
#pragma unroll
        for (int ks = 0; ks < 8; ks++) {
#pragma unroll
            for (int ntp = 0; ntp < 4; ntp++) {
                unsigned b0, b1, b2, b3;
                ldsm4(b0, b1, b2, b3, kAddr + ntp * (16 * 68 * 4) + ks * 32);
                mma_tf32(s[2 * ntp + 0], qf[ks], b0, b1);
                mma_tf32(s[2 * ntp + 1], qf[ks], b2, b3);
            }
        }

        // ---- online softmax (rows g and g+8; quad-local shuffles) ----
        float mx0 = -1e30f, mx1 = -1e30f;
#pragma unroll
        for (int nt = 0; nt < 8; nt++) {
            mx0 = fmaxf(mx0, fmaxf(s[nt][0], s[nt][1]));
            mx1 = fmaxf(mx1, fmaxf(s[nt][2], s[nt][3]));
        }
        mx0 = fmaxf(mx0, __shfl_xor_sync(0xffffffffu, mx0, 1));
        mx0 = fmaxf(mx0, __shfl_xor_sync(0xffffffffu, mx0, 2));
        mx1 = fmaxf(mx1, __shfl_xor_sync(0xffffffffu, mx1, 1));
        mx1 = fmaxf(mx1, __shfl_xor_sync(0xffffffffu, mx1, 2));
        float mn0 = fmaxf(mi0, mx0);
        float mn1 = fmaxf(mi1, mx1);
        float al0 = __expf(mi0 - mn0);
        float al1 = __expf(mi1 - mn1);
        mi0 = mn0; mi1 = mn1;

        float sum0 = 0.f, sum1 = 0.f;
#pragma unroll
        for (int nt = 0; nt < 8; nt++) {
            s[nt][0] = __expf(s[nt][0] - mn0);
            s[nt][1] = __expf(s[nt][1] - mn0);
            s[nt][2] = __expf(s[nt][2] - mn1);
            s[nt][3] = __expf(s[nt][3] - mn1);
            sum0 += s[nt][0] + s[nt][1];
            sum1 += s[nt][2] + s[nt][3];
        }
        sum0 += __shfl_xor_sync(0xffffffffu, sum0, 1);
        sum0 += __shfl_xor_sync(0xffffffffu, sum0, 2);
        sum1 += __shfl_xor_sync(0xffffffffu, sum1, 1);
        sum1 += __shfl_xor_sync(0xffffffffu, sum1, 2);
        li0 = li0 * al0 + sum0;
        li1 = li1 * al1 + sum1;

#pragma unroll
        for (int nt = 0; nt < 8; nt++) {
            o[nt][0] *= al0; o[nt][1] *= al0;
            o[nt][2] *= al1; o[nt][3] *= al1;
        }

        // ---- store P (warp-private), reload as A-fragments ----
#pragma unroll
        for (int nt = 0; nt < 8; nt++) {
            float2 v0; v0.x = f2tff(s[nt][0]); v0.y = f2tff(s[nt][1]);
            float2 v1; v1.x = f2tff(s[nt][2]); v1.y = f2tff(s[nt][3]);
            *(float2*)(p0base + 8 * nt) = v0;
            *(float2*)(p1base + 8 * nt) = v1;
        }
        __syncwarp();

        // ---- O += P V ----
#pragma unroll
        for (int ks = 0; ks < 8; ks++) {
            unsigned pf[4];
            ldsm4(pf[0], pf[1], pf[2], pf[3], aAddr + ks * 32);
#pragma unroll
            for (int ntp = 0; ntp < 4; ntp++) {
                unsigned b0, b1, b2, b3;
                ldsm4(b0, b1, b2, b3, vAddr + ntp * (16 * 68 * 4) + ks * 32);
                mma_tf32(o[2 * ntp + 0], pf, b0, b1);
                mma_tf32(o[2 * ntp + 1], pf, b2, b3);
            }
        }
    }

    // ---- normalize + writeback ----
    float inv0 = 1.f / li0;
    float inv1 = 1.f / li1;
    int r0 = q0 + 16 * w + g;
    int r1 = r0 + 8;
#pragma unroll
    for (int nt = 0; nt < 8; nt++) {
        int c = h * HD + 8 * nt + 2 * q;
        float2 v0; v0.x = o[nt][0] * inv0; v0.y = o[nt][1] * inv0;
        float2 v1; v1.x = o[nt][2] * inv1; v1.y = o[nt][3] * inv1;
        *(float2*)(g_att + (size_t)r0 * CDIM + c) = v0;
        *(float2*)(g_att + (size_t)r1 * CDIM + c) = v1;
    }
}

// ---------------------------------------------------------------------------
extern "C" void kernel_launch(void* const* d_in, const int* in_sizes, int n_in,
                              void* d_out, int out_size) {
    const float* x         = (const float*)d_in[0];
    const float* templates = (const float*)d_in[1];
    const float* coeffs    = (const float*)d_in[2];
    const float* qkv_bias  = (const float*)d_in[3];
    const float* proj_w    = (const float*)d_in[4];
    const float* proj_b    = (const float*)d_in[5];
    float* out = (float*)d_out;

    k_build_w<<<(C3 * CDIM / 4 + 255) / 256, 256>>>(templates, coeffs);

    k_gemm_qkv<<<dim3(C3 / 128, NTOK / 128), 256>>>(x, qkv_bias);

    int smem = 256 * 68 * (int)sizeof(float);   // 69632 B
    cudaFuncSetAttribute(k_flash, cudaFuncAttributeMaxDynamicSharedMemorySize, smem);
    k_flash<<<dim3(NTOK / 128, NH), 256, smem>>>();

    k_gemm_proj<<<dim3(CDIM / 128, NTOK / 128), 256>>>(proj_w, proj_b, out);
}